// round 1
// baseline (speedup 1.0000x reference)
#include <cuda_runtime.h>
#include <cuda_bf16.h>

#define N_NODES 50000
#define N_EDGES 800000
#define NFEAT 128
#define NHID 128
#define BN_EPS 1e-5f

// ---------------- scratch (static device globals; no allocation) ------------
__device__ float g_agg[(size_t)N_NODES * NFEAT];   // x + scatter-sum
__device__ float g_h[(size_t)N_NODES * NHID];      // relu(agg @ W1^T + b1)
__device__ float g_sum[NHID];                      // column sums of h
__device__ float g_sumsq[NHID];                    // column sumsq of h
__device__ float g_W2p[NHID * NHID];               // W2 with BN scale folded
__device__ float g_c2[NHID];                       // b2 with BN shift folded

// ---------------- kernel 1: agg = x, zero stats -----------------------------
__global__ void init_kernel(const float* __restrict__ x) {
    int idx = blockIdx.x * blockDim.x + threadIdx.x;   // float4 index
    const int n4 = N_NODES * NFEAT / 4;
    if (idx < n4) {
        ((float4*)g_agg)[idx] = ((const float4*)x)[idx];
    }
    if (blockIdx.x == 0 && threadIdx.x < NHID) {
        g_sum[threadIdx.x] = 0.f;
        g_sumsq[threadIdx.x] = 0.f;
    }
}

// ---------------- kernel 2: edge scatter  agg[dst] += x[src] ----------------
// One warp per edge; lane handles one float4 of the 128-float feature row.
// red.global.add.v4.f32 (sm_90+) : 1 atomic op per 16 bytes.
__global__ __launch_bounds__(256) void scatter_kernel(
    const float* __restrict__ x, const int* __restrict__ ei) {
    int warp = (blockIdx.x * blockDim.x + threadIdx.x) >> 5;
    int lane = threadIdx.x & 31;
    if (warp >= N_EDGES) return;
    int src = ei[warp];
    int dst = ei[N_EDGES + warp];
    float4 v = ((const float4*)(x + (size_t)src * NFEAT))[lane];
    float* p = g_agg + (size_t)dst * NFEAT + lane * 4;
    asm volatile("red.global.add.v4.f32 [%0], {%1, %2, %3, %4};"
                 :: "l"(p), "f"(v.x), "f"(v.y), "f"(v.z), "f"(v.w)
                 : "memory");
}

// ---------------- GEMM: out[r][n] = relu?( A[r,:] . W[n,:] + bias[n] ) ------
// 128 threads/block, thread n owns output column n: W row n lives in 32
// float4 registers. A tile (BM=64 rows x 128) staged in SMEM; all lanes
// broadcast-read the same A value -> conflict free. 8 independent FMA chains.
#define GEMM_BM 64

template <bool RELU_STATS>
__global__ __launch_bounds__(128) void gemm_kernel(
    const float* __restrict__ A, const float* __restrict__ W,
    const float* __restrict__ bias, float* __restrict__ out) {
    __shared__ float4 Ash[GEMM_BM * 32];   // 32 KB

    const int n = threadIdx.x;             // output column 0..127
    const int row0 = blockIdx.x * GEMM_BM;
    const int rows = min(GEMM_BM, N_NODES - row0);

    // W row n -> registers
    float4 w[32];
    const float4* Wrow = (const float4*)(W + n * NHID);
#pragma unroll
    for (int i = 0; i < 32; i++) w[i] = Wrow[i];
    const float bn = bias[n];

    // stage A tile (coalesced)
    const float4* Ag = (const float4*)(A + (size_t)row0 * NFEAT);
    for (int idx = threadIdx.x; idx < rows * 32; idx += 128) Ash[idx] = Ag[idx];
    __syncthreads();

    float s1 = 0.f, s2 = 0.f;
    int r = 0;
    for (; r + 2 <= rows; r += 2) {
        const float4* A0 = Ash + r * 32;
        const float4* A1 = Ash + (r + 1) * 32;
        float a0 = 0.f, a1 = 0.f, a2 = 0.f, a3 = 0.f;
        float c0 = 0.f, c1 = 0.f, c2 = 0.f, c3 = 0.f;
#pragma unroll
        for (int i = 0; i < 32; i++) {
            float4 x0 = A0[i];
            float4 x1 = A1[i];
            float4 ww = w[i];
            a0 += x0.x * ww.x; a1 += x0.y * ww.y;
            a2 += x0.z * ww.z; a3 += x0.w * ww.w;
            c0 += x1.x * ww.x; c1 += x1.y * ww.y;
            c2 += x1.z * ww.z; c3 += x1.w * ww.w;
        }
        float h0 = bn + (a0 + a1) + (a2 + a3);
        float h1 = bn + (c0 + c1) + (c2 + c3);
        if (RELU_STATS) {
            h0 = fmaxf(h0, 0.f); h1 = fmaxf(h1, 0.f);
            s1 += h0 + h1; s2 += h0 * h0 + h1 * h1;
        }
        out[(size_t)(row0 + r) * NHID + n] = h0;
        out[(size_t)(row0 + r + 1) * NHID + n] = h1;
    }
    for (; r < rows; r++) {   // odd tail
        const float4* A0 = Ash + r * 32;
        float a0 = 0.f, a1 = 0.f, a2 = 0.f, a3 = 0.f;
#pragma unroll
        for (int i = 0; i < 32; i++) {
            float4 x0 = A0[i]; float4 ww = w[i];
            a0 += x0.x * ww.x; a1 += x0.y * ww.y;
            a2 += x0.z * ww.z; a3 += x0.w * ww.w;
        }
        float h0 = bn + (a0 + a1) + (a2 + a3);
        if (RELU_STATS) { h0 = fmaxf(h0, 0.f); s1 += h0; s2 += h0 * h0; }
        out[(size_t)(row0 + r) * NHID + n] = h0;
    }
    if (RELU_STATS) {
        atomicAdd(&g_sum[n], s1);
        atomicAdd(&g_sumsq[n], s2);
    }
}

// ---------------- kernel 4: BN stats -> fold into W2 / c2 -------------------
__global__ __launch_bounds__(128) void finalize_kernel(
    const float* __restrict__ gamma, const float* __restrict__ beta,
    const float* __restrict__ W2, const float* __restrict__ b2) {
    __shared__ float sA[NHID], sB[NHID];
    int t = threadIdx.x;
    float mean = g_sum[t] * (1.f / N_NODES);
    float var  = g_sumsq[t] * (1.f / N_NODES) - mean * mean;   // biased
    float a = gamma[t] * rsqrtf(var + BN_EPS);
    float b = beta[t] - mean * a;
    sA[t] = a; sB[t] = b;
    __syncthreads();
    // thread t handles output row n = t of W2
    float c = b2[t];
    const float4* w2r = (const float4*)(W2 + t * NHID);
    float4* w2p = (float4*)(g_W2p + t * NHID);
#pragma unroll 8
    for (int i = 0; i < 32; i++) {
        float4 w = w2r[i];
        int k = i * 4;
        c += sB[k] * w.x + sB[k + 1] * w.y + sB[k + 2] * w.z + sB[k + 3] * w.w;
        w.x *= sA[k]; w.y *= sA[k + 1]; w.z *= sA[k + 2]; w.w *= sA[k + 3];
        w2p[i] = w;
    }
    g_c2[t] = c;
}

// ---------------- launch ----------------------------------------------------
extern "C" void kernel_launch(void* const* d_in, const int* in_sizes, int n_in,
                              void* d_out, int out_size) {
    const float* x     = (const float*)d_in[0];
    const int*   ei    = (const int*)d_in[1];   // JAX default: int64 -> int32
    const float* W1    = (const float*)d_in[2];
    const float* b1    = (const float*)d_in[3];
    const float* gamma = (const float*)d_in[4];
    const float* beta  = (const float*)d_in[5];
    const float* W2    = (const float*)d_in[6];
    const float* b2    = (const float*)d_in[7];
    float* out = (float*)d_out;

    float* agg_p; cudaGetSymbolAddress((void**)&agg_p, g_agg);
    float* h_p;   cudaGetSymbolAddress((void**)&h_p, g_h);
    float* w2p_p; cudaGetSymbolAddress((void**)&w2p_p, g_W2p);
    float* c2_p;  cudaGetSymbolAddress((void**)&c2_p, g_c2);

    const int n4 = N_NODES * NFEAT / 4;
    init_kernel<<<(n4 + 255) / 256, 256>>>(x);

    // one warp per edge: 800000 warps -> 100000 blocks of 8 warps
    scatter_kernel<<<N_EDGES / 8, 256>>>(x, ei);

    const int gblocks = (N_NODES + GEMM_BM - 1) / GEMM_BM;
    gemm_kernel<true><<<gblocks, 128>>>(agg_p, W1, b1, h_p);

    finalize_kernel<<<1, 128>>>(gamma, beta, W2, b2);

    gemm_kernel<false><<<gblocks, 128>>>(h_p, w2p_p, c2_p, out);
}

// round 2
// speedup vs baseline: 1.3861x; 1.3861x over previous
#include <cuda_runtime.h>
#include <cuda_bf16.h>

#define N_NODES 50000
#define N_EDGES 800000
#define NFEAT 128
#define NHID 128
#define BN_EPS 1e-5f

// ---------------- scratch (static device globals; no allocation) ------------
__device__ float g_agg[(size_t)N_NODES * NFEAT];   // x + neighbor sum
__device__ float g_h[(size_t)N_NODES * NHID];      // relu(agg @ W1^T + b1)
__device__ float g_sum[NHID];                      // column sums of h
__device__ float g_sumsq[NHID];                    // column sumsq of h
__device__ int   g_count[N_NODES];                 // in-degree histogram
__device__ int   g_off[N_NODES];                   // CSR row offsets (exclusive)
__device__ int   g_cursor[N_NODES];                // scatter cursors
__device__ int   g_srcsorted[N_EDGES];             // src ids grouped by dst

// ---------------- kernel 1: zero histogram + stats --------------------------
__global__ void zero_kernel() {
    int i = blockIdx.x * blockDim.x + threadIdx.x;
    if (i < N_NODES) g_count[i] = 0;
    if (blockIdx.x == 0 && threadIdx.x < NHID) {
        g_sum[threadIdx.x] = 0.f;
        g_sumsq[threadIdx.x] = 0.f;
    }
}

// ---------------- kernel 2: histogram of dst --------------------------------
__global__ __launch_bounds__(256) void hist_kernel(const int* __restrict__ ei) {
    int idx = blockIdx.x * blockDim.x + threadIdx.x;      // int4 index
    const int n4 = N_EDGES / 4;
    if (idx >= n4) return;
    int4 d = ((const int4*)(ei + N_EDGES))[idx];
    atomicAdd(&g_count[d.x], 1);
    atomicAdd(&g_count[d.y], 1);
    atomicAdd(&g_count[d.z], 1);
    atomicAdd(&g_count[d.w], 1);
}

// ---------------- kernel 3: exclusive scan (single block) -------------------
#define SCAN_T 1024
#define SCAN_CHUNK 49   // 49*1024 = 50176 >= 50000
__global__ __launch_bounds__(SCAN_T) void scan_kernel() {
    __shared__ int ps[SCAN_T];
    int t = threadIdx.x;
    int start = t * SCAN_CHUNK;
    int end = min(start + SCAN_CHUNK, N_NODES);
    int s = 0;
    for (int i = start; i < end; i++) s += g_count[i];
    ps[t] = s;
    __syncthreads();
    // Hillis-Steele inclusive scan over 1024 partials
    for (int off = 1; off < SCAN_T; off <<= 1) {
        int v = (t >= off) ? ps[t - off] : 0;
        __syncthreads();
        ps[t] += v;
        __syncthreads();
    }
    int run = ps[t] - s;   // exclusive base for this chunk
    for (int i = start; i < end; i++) {
        g_off[i] = run;
        g_cursor[i] = run;
        run += g_count[i];
    }
}

// ---------------- kernel 4: reorder src by dst ------------------------------
__global__ __launch_bounds__(256) void reorder_kernel(const int* __restrict__ ei) {
    int idx = blockIdx.x * blockDim.x + threadIdx.x;      // int4 index
    const int n4 = N_EDGES / 4;
    if (idx >= n4) return;
    int4 s = ((const int4*)ei)[idx];
    int4 d = ((const int4*)(ei + N_EDGES))[idx];
    g_srcsorted[atomicAdd(&g_cursor[d.x], 1)] = s.x;
    g_srcsorted[atomicAdd(&g_cursor[d.y], 1)] = s.y;
    g_srcsorted[atomicAdd(&g_cursor[d.z], 1)] = s.z;
    g_srcsorted[atomicAdd(&g_cursor[d.w], 1)] = s.w;
}

// ---------------- kernel 5: pull-aggregate (warp per node) ------------------
// agg[i] = x[i] + sum_j x[srcsorted[off[i]+j]]. No atomics.
__global__ __launch_bounds__(256) void gather_kernel(const float* __restrict__ x) {
    int warp = (blockIdx.x * blockDim.x + threadIdx.x) >> 5;
    int lane = threadIdx.x & 31;
    if (warp >= N_NODES) return;
    int start = g_off[warp];
    int deg = g_count[warp];
    float4 acc = ((const float4*)(x + (size_t)warp * NFEAT))[lane];
    const int* sl = g_srcsorted + start;
    int j = 0;
    for (; j + 2 <= deg; j += 2) {
        int s0 = sl[j], s1 = sl[j + 1];
        float4 v0 = ((const float4*)(x + (size_t)s0 * NFEAT))[lane];
        float4 v1 = ((const float4*)(x + (size_t)s1 * NFEAT))[lane];
        acc.x += v0.x; acc.y += v0.y; acc.z += v0.z; acc.w += v0.w;
        acc.x += v1.x; acc.y += v1.y; acc.z += v1.z; acc.w += v1.w;
    }
    if (j < deg) {
        int s0 = sl[j];
        float4 v0 = ((const float4*)(x + (size_t)s0 * NFEAT))[lane];
        acc.x += v0.x; acc.y += v0.y; acc.z += v0.z; acc.w += v0.w;
    }
    ((float4*)(g_agg + (size_t)warp * NFEAT))[lane] = acc;
}

// ---------------- GEMM: out[r][n] = A[r,:] . W[n,:] + bias ------------------
// FIRST: relu + accumulate BN stats. !FIRST: fold BN (a,b from stats) into
// the register-resident W2 row + bias, computed per-block in the prologue.
#define GEMM_BM 64

template <bool FIRST>
__global__ __launch_bounds__(128) void gemm_kernel(
    const float* __restrict__ A, const float* __restrict__ W,
    const float* __restrict__ bias, float* __restrict__ out,
    const float* __restrict__ gamma, const float* __restrict__ beta) {
    __shared__ float4 Ash[GEMM_BM * 32];   // 32 KB
    __shared__ float sA[NHID], sB[NHID];

    const int n = threadIdx.x;             // output column 0..127
    const int row0 = blockIdx.x * GEMM_BM;
    const int rows = min(GEMM_BM, N_NODES - row0);

    float4 w[32];
    const float4* Wrow = (const float4*)(W + n * NHID);
    float bn;
    if (FIRST) {
#pragma unroll
        for (int i = 0; i < 32; i++) w[i] = Wrow[i];
        bn = bias[n];
    } else {
        // BN fold: a[k] = gamma[k]*rsqrt(var+eps); b[k] = beta[k]-mean*a[k]
        float mean = g_sum[n] * (1.f / N_NODES);
        float var = g_sumsq[n] * (1.f / N_NODES) - mean * mean;
        float a = gamma[n] * rsqrtf(var + BN_EPS);
        sA[n] = a;
        sB[n] = beta[n] - mean * a;
        __syncthreads();
        float c = bias[n];
#pragma unroll
        for (int i = 0; i < 32; i++) {
            float4 ww = Wrow[i];
            int k = i * 4;
            c += sB[k] * ww.x + sB[k + 1] * ww.y + sB[k + 2] * ww.z + sB[k + 3] * ww.w;
            ww.x *= sA[k]; ww.y *= sA[k + 1]; ww.z *= sA[k + 2]; ww.w *= sA[k + 3];
            w[i] = ww;
        }
        bn = c;
    }

    // stage A tile (coalesced)
    const float4* Ag = (const float4*)(A + (size_t)row0 * NFEAT);
    for (int idx = threadIdx.x; idx < rows * 32; idx += 128) Ash[idx] = Ag[idx];
    __syncthreads();

    float s1 = 0.f, s2 = 0.f;
    int r = 0;
    for (; r + 2 <= rows; r += 2) {
        const float4* A0 = Ash + r * 32;
        const float4* A1 = Ash + (r + 1) * 32;
        float a0 = 0.f, a1 = 0.f, a2 = 0.f, a3 = 0.f;
        float c0 = 0.f, c1 = 0.f, c2 = 0.f, c3 = 0.f;
#pragma unroll
        for (int i = 0; i < 32; i++) {
            float4 x0 = A0[i];
            float4 x1 = A1[i];
            float4 ww = w[i];
            a0 += x0.x * ww.x; a1 += x0.y * ww.y;
            a2 += x0.z * ww.z; a3 += x0.w * ww.w;
            c0 += x1.x * ww.x; c1 += x1.y * ww.y;
            c2 += x1.z * ww.z; c3 += x1.w * ww.w;
        }
        float h0 = bn + (a0 + a1) + (a2 + a3);
        float h1 = bn + (c0 + c1) + (c2 + c3);
        if (FIRST) {
            h0 = fmaxf(h0, 0.f); h1 = fmaxf(h1, 0.f);
            s1 += h0 + h1; s2 += h0 * h0 + h1 * h1;
        }
        out[(size_t)(row0 + r) * NHID + n] = h0;
        out[(size_t)(row0 + r + 1) * NHID + n] = h1;
    }
    for (; r < rows; r++) {   // odd tail
        const float4* A0 = Ash + r * 32;
        float a0 = 0.f, a1 = 0.f, a2 = 0.f, a3 = 0.f;
#pragma unroll
        for (int i = 0; i < 32; i++) {
            float4 x0 = A0[i]; float4 ww = w[i];
            a0 += x0.x * ww.x; a1 += x0.y * ww.y;
            a2 += x0.z * ww.z; a3 += x0.w * ww.w;
        }
        float h0 = bn + (a0 + a1) + (a2 + a3);
        if (FIRST) { h0 = fmaxf(h0, 0.f); s1 += h0; s2 += h0 * h0; }
        out[(size_t)(row0 + r) * NHID + n] = h0;
    }
    if (FIRST) {
        atomicAdd(&g_sum[n], s1);
        atomicAdd(&g_sumsq[n], s2);
    }
}

// ---------------- launch ----------------------------------------------------
extern "C" void kernel_launch(void* const* d_in, const int* in_sizes, int n_in,
                              void* d_out, int out_size) {
    const float* x     = (const float*)d_in[0];
    const int*   ei    = (const int*)d_in[1];   // int32 (JAX default x64 off)
    const float* W1    = (const float*)d_in[2];
    const float* b1    = (const float*)d_in[3];
    const float* gamma = (const float*)d_in[4];
    const float* beta  = (const float*)d_in[5];
    const float* W2    = (const float*)d_in[6];
    const float* b2    = (const float*)d_in[7];
    float* out = (float*)d_out;

    float* agg_p; cudaGetSymbolAddress((void**)&agg_p, g_agg);
    float* h_p;   cudaGetSymbolAddress((void**)&h_p, g_h);

    zero_kernel<<<(N_NODES + 255) / 256, 256>>>();

    const int e4blocks = (N_EDGES / 4 + 255) / 256;
    hist_kernel<<<e4blocks, 256>>>(ei);
    scan_kernel<<<1, SCAN_T>>>();
    reorder_kernel<<<e4blocks, 256>>>(ei);

    // warp per node: 8 warps per 256-thread block
    gather_kernel<<<(N_NODES + 7) / 8, 256>>>(x);

    const int gblocks = (N_NODES + GEMM_BM - 1) / GEMM_BM;
    gemm_kernel<true><<<gblocks, 128>>>(agg_p, W1, b1, h_p, nullptr, nullptr);
    gemm_kernel<false><<<gblocks, 128>>>(h_p, W2, b2, out, gamma, beta);
}

// round 3
// speedup vs baseline: 1.3930x; 1.0050x over previous
#include <cuda_runtime.h>
#include <cuda_bf16.h>

#define N_NODES 50000
#define N_EDGES 800000
#define NFEAT 128
#define NHID 128
#define BN_EPS 1e-5f

typedef unsigned long long u64;

// packed fp32x2 helpers (sm_100+)
__device__ __forceinline__ u64 ffma2(u64 a, u64 b, u64 c) {
    u64 d;
    asm("fma.rn.f32x2 %0, %1, %2, %3;" : "=l"(d) : "l"(a), "l"(b), "l"(c));
    return d;
}
__device__ __forceinline__ float2 unpack2(u64 v) {
    float2 f;
    asm("mov.b64 {%0, %1}, %2;" : "=f"(f.x), "=f"(f.y) : "l"(v));
    return f;
}
__device__ __forceinline__ u64 pack2(float a, float b) {
    u64 v;
    asm("mov.b64 %0, {%1, %2};" : "=l"(v) : "f"(a), "f"(b));
    return v;
}

// ---------------- scratch (static device globals; no allocation) ------------
__device__ float g_agg[(size_t)N_NODES * NFEAT];   // x + neighbor sum
__device__ float g_h[(size_t)N_NODES * NHID];      // relu(agg @ W1^T + b1)
__device__ float g_sum[NHID];                      // column sums of h
__device__ float g_sumsq[NHID];                    // column sumsq of h
__device__ int   g_count[N_NODES];                 // in-degree histogram
__device__ int   g_off[N_NODES];                   // CSR row offsets (exclusive)
__device__ int   g_cursor[N_NODES];                // scatter cursors
__device__ int   g_srcsorted[N_EDGES];             // src ids grouped by dst

// ---------------- kernel 1: zero histogram ----------------------------------
__global__ void zero_kernel() {
    int i = blockIdx.x * blockDim.x + threadIdx.x;
    if (i < N_NODES) g_count[i] = 0;
}

// ---------------- kernel 2: histogram of dst --------------------------------
__global__ __launch_bounds__(256) void hist_kernel(const int* __restrict__ ei) {
    int idx = blockIdx.x * blockDim.x + threadIdx.x;      // int4 index
    const int n4 = N_EDGES / 4;
    if (idx >= n4) return;
    int4 d = ((const int4*)(ei + N_EDGES))[idx];
    atomicAdd(&g_count[d.x], 1);
    atomicAdd(&g_count[d.y], 1);
    atomicAdd(&g_count[d.z], 1);
    atomicAdd(&g_count[d.w], 1);
}

// ---------------- kernel 3: exclusive scan (single block) + zero stats ------
#define SCAN_T 1024
#define SCAN_CHUNK 49   // 49*1024 = 50176 >= 50000
__global__ __launch_bounds__(SCAN_T) void scan_kernel() {
    __shared__ int ps[SCAN_T];
    int t = threadIdx.x;
    if (t < NHID) { g_sum[t] = 0.f; g_sumsq[t] = 0.f; }
    int start = t * SCAN_CHUNK;
    int end = min(start + SCAN_CHUNK, N_NODES);
    int s = 0;
    for (int i = start; i < end; i++) s += g_count[i];
    ps[t] = s;
    __syncthreads();
    for (int off = 1; off < SCAN_T; off <<= 1) {
        int v = (t >= off) ? ps[t - off] : 0;
        __syncthreads();
        ps[t] += v;
        __syncthreads();
    }
    int run = ps[t] - s;   // exclusive base for this chunk
    for (int i = start; i < end; i++) {
        g_off[i] = run;
        g_cursor[i] = run;
        run += g_count[i];
    }
}

// ---------------- kernel 4: reorder src by dst ------------------------------
__global__ __launch_bounds__(256) void reorder_kernel(const int* __restrict__ ei) {
    int idx = blockIdx.x * blockDim.x + threadIdx.x;      // int4 index
    const int n4 = N_EDGES / 4;
    if (idx >= n4) return;
    int4 s = ((const int4*)ei)[idx];
    int4 d = ((const int4*)(ei + N_EDGES))[idx];
    g_srcsorted[atomicAdd(&g_cursor[d.x], 1)] = s.x;
    g_srcsorted[atomicAdd(&g_cursor[d.y], 1)] = s.y;
    g_srcsorted[atomicAdd(&g_cursor[d.z], 1)] = s.z;
    g_srcsorted[atomicAdd(&g_cursor[d.w], 1)] = s.w;
}

// ---------------- kernel 5: pull-aggregate (warp per node) ------------------
__global__ __launch_bounds__(256) void gather_kernel(const float* __restrict__ x) {
    int warp = (blockIdx.x * blockDim.x + threadIdx.x) >> 5;
    int lane = threadIdx.x & 31;
    if (warp >= N_NODES) return;
    int start = g_off[warp];
    int deg = g_count[warp];
    float4 acc = ((const float4*)(x + (size_t)warp * NFEAT))[lane];
    const int* sl = g_srcsorted + start;
    int j = 0;
    for (; j + 4 <= deg; j += 4) {
        int s0 = sl[j], s1 = sl[j + 1], s2 = sl[j + 2], s3 = sl[j + 3];
        float4 v0 = ((const float4*)(x + (size_t)s0 * NFEAT))[lane];
        float4 v1 = ((const float4*)(x + (size_t)s1 * NFEAT))[lane];
        float4 v2 = ((const float4*)(x + (size_t)s2 * NFEAT))[lane];
        float4 v3 = ((const float4*)(x + (size_t)s3 * NFEAT))[lane];
        acc.x += v0.x + v1.x + v2.x + v3.x;
        acc.y += v0.y + v1.y + v2.y + v3.y;
        acc.z += v0.z + v1.z + v2.z + v3.z;
        acc.w += v0.w + v1.w + v2.w + v3.w;
    }
    for (; j < deg; j++) {
        int s0 = sl[j];
        float4 v0 = ((const float4*)(x + (size_t)s0 * NFEAT))[lane];
        acc.x += v0.x; acc.y += v0.y; acc.z += v0.z; acc.w += v0.w;
    }
    ((float4*)(g_agg + (size_t)warp * NFEAT))[lane] = acc;
}

// ---------------- GEMM via packed f32x2 FMA ---------------------------------
// Thread n owns output column n; W row n in 32 ulonglong2 regs (k-pairs).
// A tile staged in SMEM, broadcast-read as k-pairs. 4 FFMA2 chains / 2 rows.
#define GEMM_BM 64

template <bool FIRST>
__global__ __launch_bounds__(128) void gemm_kernel(
    const float* __restrict__ A, const float* __restrict__ W,
    const float* __restrict__ bias, float* __restrict__ out,
    const float* __restrict__ gamma, const float* __restrict__ beta) {
    __shared__ float4 Ash[GEMM_BM * 32];   // 32 KB
    __shared__ float sA[NHID], sB[NHID];

    const int n = threadIdx.x;             // output column 0..127
    const int row0 = blockIdx.x * GEMM_BM;
    const int rows = min(GEMM_BM, N_NODES - row0);  // 64 or 16: always even

    ulonglong2 w[32];
    const ulonglong2* Wrow = (const ulonglong2*)(W + n * NHID);
    float bn;
    if (FIRST) {
#pragma unroll
        for (int i = 0; i < 32; i++) w[i] = Wrow[i];
        bn = bias[n];
    } else {
        // BN fold: a[k] = gamma[k]*rsqrt(var+eps); b[k] = beta[k]-mean*a[k]
        float mean = g_sum[n] * (1.f / N_NODES);
        float var = g_sumsq[n] * (1.f / N_NODES) - mean * mean;
        float a = gamma[n] * rsqrtf(var + BN_EPS);
        sA[n] = a;
        sB[n] = beta[n] - mean * a;
        __syncthreads();
        float c = bias[n];
        const float4* Wf = (const float4*)Wrow;
#pragma unroll
        for (int i = 0; i < 32; i++) {
            float4 ww = Wf[i];
            int k = i * 4;
            c += sB[k] * ww.x + sB[k + 1] * ww.y + sB[k + 2] * ww.z + sB[k + 3] * ww.w;
            ww.x *= sA[k]; ww.y *= sA[k + 1]; ww.z *= sA[k + 2]; ww.w *= sA[k + 3];
            w[i].x = pack2(ww.x, ww.y);
            w[i].y = pack2(ww.z, ww.w);
        }
        bn = c;
    }

    // stage A tile (coalesced)
    const float4* Ag = (const float4*)(A + (size_t)row0 * NFEAT);
    for (int idx = threadIdx.x; idx < rows * 32; idx += 128) Ash[idx] = Ag[idx];
    __syncthreads();

    float s1 = 0.f, s2 = 0.f;
    for (int r = 0; r < rows; r += 2) {
        const ulonglong2* A0 = (const ulonglong2*)(Ash + r * 32);
        const ulonglong2* A1 = (const ulonglong2*)(Ash + (r + 1) * 32);
        u64 a01 = pack2(bn, 0.f), a23 = 0ull;
        u64 b01 = pack2(bn, 0.f), b23 = 0ull;
#pragma unroll
        for (int i = 0; i < 32; i++) {
            ulonglong2 x0 = A0[i];
            ulonglong2 x1 = A1[i];
            ulonglong2 ww = w[i];
            a01 = ffma2(x0.x, ww.x, a01);
            a23 = ffma2(x0.y, ww.y, a23);
            b01 = ffma2(x1.x, ww.x, b01);
            b23 = ffma2(x1.y, ww.y, b23);
        }
        float2 pa = unpack2(a01), qa = unpack2(a23);
        float2 pb = unpack2(b01), qb = unpack2(b23);
        float h0 = (pa.x + pa.y) + (qa.x + qa.y);
        float h1 = (pb.x + pb.y) + (qb.x + qb.y);
        if (FIRST) {
            h0 = fmaxf(h0, 0.f); h1 = fmaxf(h1, 0.f);
            s1 += h0 + h1; s2 += h0 * h0 + h1 * h1;
        }
        out[(size_t)(row0 + r) * NHID + n] = h0;
        out[(size_t)(row0 + r + 1) * NHID + n] = h1;
    }
    if (FIRST) {
        atomicAdd(&g_sum[n], s1);
        atomicAdd(&g_sumsq[n], s2);
    }
}

// ---------------- launch ----------------------------------------------------
extern "C" void kernel_launch(void* const* d_in, const int* in_sizes, int n_in,
                              void* d_out, int out_size) {
    const float* x     = (const float*)d_in[0];
    const int*   ei    = (const int*)d_in[1];   // int32 (JAX default x64 off)
    const float* W1    = (const float*)d_in[2];
    const float* b1    = (const float*)d_in[3];
    const float* gamma = (const float*)d_in[4];
    const float* beta  = (const float*)d_in[5];
    const float* W2    = (const float*)d_in[6];
    const float* b2    = (const float*)d_in[7];
    float* out = (float*)d_out;

    float* agg_p; cudaGetSymbolAddress((void**)&agg_p, g_agg);
    float* h_p;   cudaGetSymbolAddress((void**)&h_p, g_h);

    zero_kernel<<<(N_NODES + 255) / 256, 256>>>();

    const int e4blocks = (N_EDGES / 4 + 255) / 256;
    hist_kernel<<<e4blocks, 256>>>(ei);
    scan_kernel<<<1, SCAN_T>>>();
    reorder_kernel<<<e4blocks, 256>>>(ei);

    gather_kernel<<<(N_NODES + 7) / 8, 256>>>(x);

    const int gblocks = (N_NODES + GEMM_BM - 1) / GEMM_BM;
    gemm_kernel<true><<<gblocks, 128>>>(agg_p, W1, b1, h_p, nullptr, nullptr);
    gemm_kernel<false><<<gblocks, 128>>>(h_p, W2, b2, out, gamma, beta);
}

// round 4
// speedup vs baseline: 1.9819x; 1.4228x over previous
#include <cuda_runtime.h>
#include <cuda_bf16.h>

#define N_NODES 50000
#define N_EDGES 800000
#define NFEAT 128
#define NHID 128
#define BN_EPS 1e-5f

#define NBLK 196          // ceil(50000/256)

typedef unsigned long long u64;

// packed fp32x2 helpers (sm_100+)
__device__ __forceinline__ u64 ffma2(u64 a, u64 b, u64 c) {
    u64 d;
    asm("fma.rn.f32x2 %0, %1, %2, %3;" : "=l"(d) : "l"(a), "l"(b), "l"(c));
    return d;
}
__device__ __forceinline__ float2 unpack2(u64 v) {
    float2 f;
    asm("mov.b64 {%0, %1}, %2;" : "=f"(f.x), "=f"(f.y) : "l"(v));
    return f;
}
__device__ __forceinline__ u64 pack2(float a, float b) {
    u64 v;
    asm("mov.b64 %0, {%1, %2};" : "=l"(v) : "f"(a), "f"(b));
    return v;
}

// ---------------- scratch (static device globals; no allocation) ------------
__device__ float g_agg[(size_t)N_NODES * NFEAT];
__device__ float g_h[(size_t)N_NODES * NHID];
__device__ float g_sum[NHID];
__device__ float g_sumsq[NHID];
__device__ int   g_count[N_NODES];          // zero-init; self-cleaned each run
__device__ int   g_off[N_NODES + 1];        // CSR offsets + sentinel
__device__ int   g_cursor[N_NODES];
__device__ int   g_srcsorted[N_EDGES];
__device__ int   g_bsum[NBLK];              // per-block count sums

// ---------------- kernel 1: histogram of dst --------------------------------
__global__ __launch_bounds__(256) void hist_kernel(const int* __restrict__ ei) {
    int idx = blockIdx.x * blockDim.x + threadIdx.x;      // int4 index
    const int n4 = N_EDGES / 4;
    if (idx >= n4) return;
    int4 d = ((const int4*)(ei + N_EDGES))[idx];
    atomicAdd(&g_count[d.x], 1);
    atomicAdd(&g_count[d.y], 1);
    atomicAdd(&g_count[d.z], 1);
    atomicAdd(&g_count[d.w], 1);
}

// ---------------- kernel 2: per-block partial sums (coalesced) --------------
__global__ __launch_bounds__(256) void partial_kernel() {
    int t = threadIdx.x;
    int i = blockIdx.x * 256 + t;
    int v = (i < N_NODES) ? g_count[i] : 0;
#pragma unroll
    for (int o = 16; o > 0; o >>= 1) v += __shfl_down_sync(~0u, v, o);
    __shared__ int ws[8];
    if ((t & 31) == 0) ws[t >> 5] = v;
    __syncthreads();
    if (t == 0) {
        int s = 0;
#pragma unroll
        for (int k = 0; k < 8; k++) s += ws[k];
        g_bsum[blockIdx.x] = s;
    }
}

// ---------------- kernel 3: offsets (block scan + redundant base scan) ------
// Writes g_off/g_cursor coalesced; zeroes g_count for next replay; zeroes BN
// stats; writes sentinel g_off[N] = E.
__global__ __launch_bounds__(256) void offsets_kernel() {
    __shared__ int sb[256];   // base scan over NBLK partials
    __shared__ int sh[256];   // local scan
    int t = threadIdx.x;
    int bid = blockIdx.x;

    // redundant exclusive scan of block partials (NBLK <= 256)
    sb[t] = (t < NBLK) ? g_bsum[t] : 0;
    __syncthreads();
#pragma unroll
    for (int o = 1; o < 256; o <<= 1) {
        int u = (t >= o) ? sb[t - o] : 0;
        __syncthreads();
        sb[t] += u;
        __syncthreads();
    }
    int base = (bid > 0) ? sb[bid - 1] : 0;   // exclusive base for this block

    // local exclusive scan of this block's 256 counts (coalesced load)
    int i = bid * 256 + t;
    int v = (i < N_NODES) ? g_count[i] : 0;
    sh[t] = v;
    __syncthreads();
#pragma unroll
    for (int o = 1; o < 256; o <<= 1) {
        int u = (t >= o) ? sh[t - o] : 0;
        __syncthreads();
        sh[t] += u;
        __syncthreads();
    }
    int off = base + sh[t] - v;   // exclusive
    if (i < N_NODES) {
        g_off[i] = off;
        g_cursor[i] = off;
        g_count[i] = 0;           // self-clean for next graph replay
    } else if (i == N_NODES) {
        g_off[N_NODES] = N_EDGES; // sentinel
    }
    if (bid == 0 && t < NHID) { g_sum[t] = 0.f; g_sumsq[t] = 0.f; }
}

// ---------------- kernel 4: reorder src by dst ------------------------------
__global__ __launch_bounds__(256) void reorder_kernel(const int* __restrict__ ei) {
    int idx = blockIdx.x * blockDim.x + threadIdx.x;      // int4 index
    const int n4 = N_EDGES / 4;
    if (idx >= n4) return;
    int4 s = ((const int4*)ei)[idx];
    int4 d = ((const int4*)(ei + N_EDGES))[idx];
    g_srcsorted[atomicAdd(&g_cursor[d.x], 1)] = s.x;
    g_srcsorted[atomicAdd(&g_cursor[d.y], 1)] = s.y;
    g_srcsorted[atomicAdd(&g_cursor[d.z], 1)] = s.z;
    g_srcsorted[atomicAdd(&g_cursor[d.w], 1)] = s.w;
}

// ---------------- kernel 5: pull-aggregate (warp per node) ------------------
__global__ __launch_bounds__(256) void gather_kernel(const float* __restrict__ x) {
    int warp = (blockIdx.x * blockDim.x + threadIdx.x) >> 5;
    int lane = threadIdx.x & 31;
    if (warp >= N_NODES) return;
    int start = g_off[warp];
    int deg = g_off[warp + 1] - start;
    float4 acc = ((const float4*)(x + (size_t)warp * NFEAT))[lane];
    const int* sl = g_srcsorted + start;
    int j = 0;
    for (; j + 4 <= deg; j += 4) {
        int s0 = sl[j], s1 = sl[j + 1], s2 = sl[j + 2], s3 = sl[j + 3];
        float4 v0 = ((const float4*)(x + (size_t)s0 * NFEAT))[lane];
        float4 v1 = ((const float4*)(x + (size_t)s1 * NFEAT))[lane];
        float4 v2 = ((const float4*)(x + (size_t)s2 * NFEAT))[lane];
        float4 v3 = ((const float4*)(x + (size_t)s3 * NFEAT))[lane];
        acc.x += v0.x + v1.x + v2.x + v3.x;
        acc.y += v0.y + v1.y + v2.y + v3.y;
        acc.z += v0.z + v1.z + v2.z + v3.z;
        acc.w += v0.w + v1.w + v2.w + v3.w;
    }
    for (; j < deg; j++) {
        int s0 = sl[j];
        float4 v0 = ((const float4*)(x + (size_t)s0 * NFEAT))[lane];
        acc.x += v0.x; acc.y += v0.y; acc.z += v0.z; acc.w += v0.w;
    }
    ((float4*)(g_agg + (size_t)warp * NFEAT))[lane] = acc;
}

// ---------------- GEMM via packed f32x2 FMA ---------------------------------
#define GEMM_BM 64

template <bool FIRST>
__global__ __launch_bounds__(128) void gemm_kernel(
    const float* __restrict__ A, const float* __restrict__ W,
    const float* __restrict__ bias, float* __restrict__ out,
    const float* __restrict__ gamma, const float* __restrict__ beta) {
    __shared__ float4 Ash[GEMM_BM * 32];   // 32 KB
    __shared__ float sA[NHID], sB[NHID];

    const int n = threadIdx.x;             // output column 0..127
    const int row0 = blockIdx.x * GEMM_BM;
    const int rows = min(GEMM_BM, N_NODES - row0);  // 64 or 16: always even

    ulonglong2 w[32];
    const ulonglong2* Wrow = (const ulonglong2*)(W + n * NHID);
    float bn;
    if (FIRST) {
#pragma unroll
        for (int i = 0; i < 32; i++) w[i] = Wrow[i];
        bn = bias[n];
    } else {
        float mean = g_sum[n] * (1.f / N_NODES);
        float var = g_sumsq[n] * (1.f / N_NODES) - mean * mean;
        float a = gamma[n] * rsqrtf(var + BN_EPS);
        sA[n] = a;
        sB[n] = beta[n] - mean * a;
        __syncthreads();
        float c = bias[n];
        const float4* Wf = (const float4*)Wrow;
#pragma unroll
        for (int i = 0; i < 32; i++) {
            float4 ww = Wf[i];
            int k = i * 4;
            c += sB[k] * ww.x + sB[k + 1] * ww.y + sB[k + 2] * ww.z + sB[k + 3] * ww.w;
            ww.x *= sA[k]; ww.y *= sA[k + 1]; ww.z *= sA[k + 2]; ww.w *= sA[k + 3];
            w[i].x = pack2(ww.x, ww.y);
            w[i].y = pack2(ww.z, ww.w);
        }
        bn = c;
    }

    const float4* Ag = (const float4*)(A + (size_t)row0 * NFEAT);
    for (int idx = threadIdx.x; idx < rows * 32; idx += 128) Ash[idx] = Ag[idx];
    __syncthreads();

    float s1 = 0.f, s2 = 0.f;
    for (int r = 0; r < rows; r += 2) {
        const ulonglong2* A0 = (const ulonglong2*)(Ash + r * 32);
        const ulonglong2* A1 = (const ulonglong2*)(Ash + (r + 1) * 32);
        u64 a01 = pack2(bn, 0.f), a23 = 0ull;
        u64 b01 = pack2(bn, 0.f), b23 = 0ull;
#pragma unroll
        for (int i = 0; i < 32; i++) {
            ulonglong2 x0 = A0[i];
            ulonglong2 x1 = A1[i];
            ulonglong2 ww = w[i];
            a01 = ffma2(x0.x, ww.x, a01);
            a23 = ffma2(x0.y, ww.y, a23);
            b01 = ffma2(x1.x, ww.x, b01);
            b23 = ffma2(x1.y, ww.y, b23);
        }
        float2 pa = unpack2(a01), qa = unpack2(a23);
        float2 pb = unpack2(b01), qb = unpack2(b23);
        float h0 = (pa.x + pa.y) + (qa.x + qa.y);
        float h1 = (pb.x + pb.y) + (qb.x + qb.y);
        if (FIRST) {
            h0 = fmaxf(h0, 0.f); h1 = fmaxf(h1, 0.f);
            s1 += h0 + h1; s2 += h0 * h0 + h1 * h1;
        }
        out[(size_t)(row0 + r) * NHID + n] = h0;
        out[(size_t)(row0 + r + 1) * NHID + n] = h1;
    }
    if (FIRST) {
        atomicAdd(&g_sum[n], s1);
        atomicAdd(&g_sumsq[n], s2);
    }
}

// ---------------- launch ----------------------------------------------------
extern "C" void kernel_launch(void* const* d_in, const int* in_sizes, int n_in,
                              void* d_out, int out_size) {
    const float* x     = (const float*)d_in[0];
    const int*   ei    = (const int*)d_in[1];   // int32 (JAX default x64 off)
    const float* W1    = (const float*)d_in[2];
    const float* b1    = (const float*)d_in[3];
    const float* gamma = (const float*)d_in[4];
    const float* beta  = (const float*)d_in[5];
    const float* W2    = (const float*)d_in[6];
    const float* b2    = (const float*)d_in[7];
    float* out = (float*)d_out;

    float* agg_p; cudaGetSymbolAddress((void**)&agg_p, g_agg);
    float* h_p;   cudaGetSymbolAddress((void**)&h_p, g_h);

    const int e4blocks = (N_EDGES / 4 + 255) / 256;
    hist_kernel<<<e4blocks, 256>>>(ei);
    partial_kernel<<<NBLK, 256>>>();
    offsets_kernel<<<NBLK, 256>>>();
    reorder_kernel<<<e4blocks, 256>>>(ei);

    gather_kernel<<<(N_NODES + 7) / 8, 256>>>(x);

    const int gblocks = (N_NODES + GEMM_BM - 1) / GEMM_BM;
    gemm_kernel<true><<<gblocks, 128>>>(agg_p, W1, b1, h_p, nullptr, nullptr);
    gemm_kernel<false><<<gblocks, 128>>>(h_p, W2, b2, out, gamma, beta);
}

// round 5
// speedup vs baseline: 2.0258x; 1.0221x over previous
#include <cuda_runtime.h>
#include <cuda_bf16.h>

#define N_NODES 50000
#define N_EDGES 800000
#define NFEAT 128
#define NHID 128
#define BN_EPS 1e-5f
#define NBLK 196          // ceil(50000/256)

typedef unsigned long long u64;

__device__ __forceinline__ u64 ffma2(u64 a, u64 b, u64 c) {
    u64 d;
    asm("fma.rn.f32x2 %0, %1, %2, %3;" : "=l"(d) : "l"(a), "l"(b), "l"(c));
    return d;
}
__device__ __forceinline__ float2 unpack2(u64 v) {
    float2 f;
    asm("mov.b64 {%0, %1}, %2;" : "=f"(f.x), "=f"(f.y) : "l"(v));
    return f;
}
__device__ __forceinline__ u64 pack2(float a, float b) {
    u64 v;
    asm("mov.b64 %0, {%1, %2};" : "=l"(v) : "f"(a), "f"(b));
    return v;
}

// ---------------- scratch ----------------------------------------------------
__device__ float g_agg[(size_t)N_NODES * NFEAT];
__device__ float g_h[(size_t)N_NODES * NHID];
__device__ float g_sum[NHID];
__device__ float g_sumsq[NHID];
__device__ int   g_count[N_NODES];          // zero-init; self-cleaned each run
__device__ int   g_off[N_NODES + 1];
__device__ int   g_cursor[N_NODES];
__device__ int   g_srcsorted[N_EDGES];
__device__ int   g_bsum[NBLK];
__device__ float g_W1T[NHID * NFEAT];       // W1^T [k][col]
__device__ float g_W2T[NHID * NHID];        // W2^T [k][col]

// ---------------- kernel: histogram of dst (8 edges/thread) -----------------
__global__ __launch_bounds__(256) void hist_kernel(const int* __restrict__ ei) {
    const int n8 = N_EDGES / 8;               // int4 pairs
    int idx = blockIdx.x * blockDim.x + threadIdx.x;
    if (idx >= n8) return;
    const int4* d4 = (const int4*)(ei + N_EDGES);
    int4 a = d4[idx];
    int4 b = d4[idx + n8];
    atomicAdd(&g_count[a.x], 1); atomicAdd(&g_count[a.y], 1);
    atomicAdd(&g_count[a.z], 1); atomicAdd(&g_count[a.w], 1);
    atomicAdd(&g_count[b.x], 1); atomicAdd(&g_count[b.y], 1);
    atomicAdd(&g_count[b.z], 1); atomicAdd(&g_count[b.w], 1);
}

// ---------------- kernel: per-block partial sums -----------------------------
__global__ __launch_bounds__(256) void partial_kernel() {
    int t = threadIdx.x;
    int i = blockIdx.x * 256 + t;
    int v = (i < N_NODES) ? g_count[i] : 0;
#pragma unroll
    for (int o = 16; o > 0; o >>= 1) v += __shfl_down_sync(~0u, v, o);
    __shared__ int ws[8];
    if ((t & 31) == 0) ws[t >> 5] = v;
    __syncthreads();
    if (t == 0) {
        int s = 0;
#pragma unroll
        for (int k = 0; k < 8; k++) s += ws[k];
        g_bsum[blockIdx.x] = s;
    }
}

// ---------------- kernel: offsets ---------------------------------------------
__global__ __launch_bounds__(256) void offsets_kernel() {
    __shared__ int sb[256];
    __shared__ int sh[256];
    int t = threadIdx.x;
    int bid = blockIdx.x;

    sb[t] = (t < NBLK) ? g_bsum[t] : 0;
    __syncthreads();
#pragma unroll
    for (int o = 1; o < 256; o <<= 1) {
        int u = (t >= o) ? sb[t - o] : 0;
        __syncthreads();
        sb[t] += u;
        __syncthreads();
    }
    int base = (bid > 0) ? sb[bid - 1] : 0;

    int i = bid * 256 + t;
    int v = (i < N_NODES) ? g_count[i] : 0;
    sh[t] = v;
    __syncthreads();
#pragma unroll
    for (int o = 1; o < 256; o <<= 1) {
        int u = (t >= o) ? sh[t - o] : 0;
        __syncthreads();
        sh[t] += u;
        __syncthreads();
    }
    int off = base + sh[t] - v;
    if (i < N_NODES) {
        g_off[i] = off;
        g_cursor[i] = off;
        g_count[i] = 0;
    } else if (i == N_NODES) {
        g_off[N_NODES] = N_EDGES;
    }
    if (bid == 0 && t < NHID) { g_sum[t] = 0.f; g_sumsq[t] = 0.f; }
}

// ---------------- kernel: reorder src by dst (8 edges/thread) -----------------
__global__ __launch_bounds__(256) void reorder_kernel(const int* __restrict__ ei) {
    const int n8 = N_EDGES / 8;
    int idx = blockIdx.x * blockDim.x + threadIdx.x;
    if (idx >= n8) return;
    const int4* s4 = (const int4*)ei;
    const int4* d4 = (const int4*)(ei + N_EDGES);
    int4 sa = s4[idx], sb = s4[idx + n8];
    int4 da = d4[idx], db = d4[idx + n8];
    g_srcsorted[atomicAdd(&g_cursor[da.x], 1)] = sa.x;
    g_srcsorted[atomicAdd(&g_cursor[da.y], 1)] = sa.y;
    g_srcsorted[atomicAdd(&g_cursor[da.z], 1)] = sa.z;
    g_srcsorted[atomicAdd(&g_cursor[da.w], 1)] = sa.w;
    g_srcsorted[atomicAdd(&g_cursor[db.x], 1)] = sb.x;
    g_srcsorted[atomicAdd(&g_cursor[db.y], 1)] = sb.y;
    g_srcsorted[atomicAdd(&g_cursor[db.z], 1)] = sb.z;
    g_srcsorted[atomicAdd(&g_cursor[db.w], 1)] = sb.w;
}

// ---------------- kernel: transpose W1, W2 ------------------------------------
__global__ __launch_bounds__(256) void transpose_kernel(
    const float* __restrict__ W1, const float* __restrict__ W2) {
    const float* src = blockIdx.x ? W2 : W1;
    float* dst = blockIdx.x ? g_W2T : g_W1T;
    for (int idx = threadIdx.x; idx < 128 * 32; idx += 256) {
        int row = idx >> 5;           // source row (= output col)
        int c4 = idx & 31;
        float4 v = ((const float4*)src)[idx];
        dst[(4 * c4 + 0) * 128 + row] = v.x;
        dst[(4 * c4 + 1) * 128 + row] = v.y;
        dst[(4 * c4 + 2) * 128 + row] = v.z;
        dst[(4 * c4 + 3) * 128 + row] = v.w;
    }
}

// ---------------- kernel: pull-aggregate (warp per node) ----------------------
__global__ __launch_bounds__(256) void gather_kernel(const float* __restrict__ x) {
    int warp = (blockIdx.x * blockDim.x + threadIdx.x) >> 5;
    int lane = threadIdx.x & 31;
    if (warp >= N_NODES) return;
    int start = g_off[warp];
    int deg = g_off[warp + 1] - start;
    float4 acc = ((const float4*)(x + (size_t)warp * NFEAT))[lane];
    const int* sl = g_srcsorted + start;
    int j = 0;
    for (; j + 4 <= deg; j += 4) {
        int s0 = sl[j], s1 = sl[j + 1], s2 = sl[j + 2], s3 = sl[j + 3];
        float4 v0 = ((const float4*)(x + (size_t)s0 * NFEAT))[lane];
        float4 v1 = ((const float4*)(x + (size_t)s1 * NFEAT))[lane];
        float4 v2 = ((const float4*)(x + (size_t)s2 * NFEAT))[lane];
        float4 v3 = ((const float4*)(x + (size_t)s3 * NFEAT))[lane];
        acc.x += v0.x + v1.x + v2.x + v3.x;
        acc.y += v0.y + v1.y + v2.y + v3.y;
        acc.z += v0.z + v1.z + v2.z + v3.z;
        acc.w += v0.w + v1.w + v2.w + v3.w;
    }
    for (; j < deg; j++) {
        int s0 = sl[j];
        float4 v0 = ((const float4*)(x + (size_t)s0 * NFEAT))[lane];
        acc.x += v0.x; acc.y += v0.y; acc.z += v0.z; acc.w += v0.w;
    }
    ((float4*)(g_agg + (size_t)warp * NFEAT))[lane] = acc;
}

// ---------------- register-blocked GEMM (8x8 micro-tile, f32x2) ---------------
// BM=64 rows x BN=128 cols per block, 128 threads: tx=tid&15 (8 cols each),
// ty=tid>>4 (8 rows each). Asm = A^T [k][row] (stride 68); Wsm = W^T [k][col].
#define AS 68
#define SMEM_W 0                   // 128*128 floats
#define SMEM_A (128 * 128)         // 128*68 floats
#define SMEM_MISC (SMEM_A + 128 * AS)
#define GEMM_SMEM_BYTES ((SMEM_MISC + 512) * 4)

template <bool FIRST>
__global__ __launch_bounds__(128) void gemm_kernel(
    const float* __restrict__ A, const float* __restrict__ WT,
    const float* __restrict__ bias, float* __restrict__ out,
    const float* __restrict__ gamma, const float* __restrict__ beta,
    const float* __restrict__ W2, const float* __restrict__ b2) {
    extern __shared__ float smem[];
    float* Wsm = smem + SMEM_W;
    float* Asm = smem + SMEM_A;
    float* sA = smem + SMEM_MISC;
    float* sB = sA + 128;
    float* sc2 = sB + 128;

    const int tid = threadIdx.x;
    const int tx = tid & 15;
    const int ty = tid >> 4;
    const int row0 = blockIdx.x * 64;
    const int rows = min(64, N_NODES - row0);

    // ---- stage W^T (with BN fold for GEMM2) ----
    if (FIRST) {
        for (int i = tid; i < 4096; i += 128)
            ((float4*)Wsm)[i] = ((const float4*)WT)[i];
    } else {
        float mean = g_sum[tid] * (1.f / N_NODES);
        float var = g_sumsq[tid] * (1.f / N_NODES) - mean * mean;
        float a = gamma[tid] * rsqrtf(var + BN_EPS);
        sA[tid] = a;
        sB[tid] = beta[tid] - mean * a;
        __syncthreads();
        // c2[col] = b2[col] + sum_k W2[col][k]*sB[k]
        float c = b2[tid];
        const float4* w2r = (const float4*)(W2 + tid * NHID);
#pragma unroll 8
        for (int i = 0; i < 32; i++) {
            float4 w = w2r[i];
            int k = i * 4;
            c += w.x * sB[k] + w.y * sB[k + 1] + w.z * sB[k + 2] + w.w * sB[k + 3];
        }
        sc2[tid] = c;
        for (int i = tid; i < 4096; i += 128) {
            int k = i >> 5;
            float4 v = ((const float4*)WT)[i];
            float a2 = sA[k];
            v.x *= a2; v.y *= a2; v.z *= a2; v.w *= a2;
            ((float4*)Wsm)[i] = v;
        }
    }

    // ---- stage A^T (lane = row: conflict-free STS) ----
#pragma unroll
    for (int iter = 0; iter < 16; iter++) {
        int idx = iter * 128 + tid;
        int row = idx & 63;
        int kg = idx >> 6;            // float4 group along k
        int grow = row0 + row;
        float4 v = make_float4(0.f, 0.f, 0.f, 0.f);
        if (grow < N_NODES) v = ((const float4*)(A + (size_t)grow * NFEAT))[kg];
        Asm[(4 * kg + 0) * AS + row] = v.x;
        Asm[(4 * kg + 1) * AS + row] = v.y;
        Asm[(4 * kg + 2) * AS + row] = v.z;
        Asm[(4 * kg + 3) * AS + row] = v.w;
    }
    __syncthreads();

    // ---- bias frag + accumulator init ----
    float cbias[8];
#pragma unroll
    for (int c = 0; c < 8; c++)
        cbias[c] = FIRST ? bias[tx * 8 + c] : sc2[tx * 8 + c];
    u64 acc[32];
#pragma unroll
    for (int rp = 0; rp < 4; rp++)
#pragma unroll
        for (int c = 0; c < 8; c++)
            acc[rp * 8 + c] = pack2(cbias[c], cbias[c]);

    // ---- mainloop ----
#pragma unroll 4
    for (int k = 0; k < 128; k++) {
        ulonglong2 apA = *(const ulonglong2*)(Asm + k * AS + ty * 8);
        ulonglong2 apB = *(const ulonglong2*)(Asm + k * AS + ty * 8 + 4);
        float4 w0 = *(const float4*)(Wsm + k * 128 + tx * 8);
        float4 w1 = *(const float4*)(Wsm + k * 128 + tx * 8 + 4);
        u64 ar[4] = {apA.x, apA.y, apB.x, apB.y};
        u64 wd[8] = {pack2(w0.x, w0.x), pack2(w0.y, w0.y),
                     pack2(w0.z, w0.z), pack2(w0.w, w0.w),
                     pack2(w1.x, w1.x), pack2(w1.y, w1.y),
                     pack2(w1.z, w1.z), pack2(w1.w, w1.w)};
#pragma unroll
        for (int rp = 0; rp < 4; rp++)
#pragma unroll
            for (int c = 0; c < 8; c++)
                acc[rp * 8 + c] = ffma2(ar[rp], wd[c], acc[rp * 8 + c]);
    }

    // ---- epilogue ----
    float s1p[8], s2p[8];
    if (FIRST) {
#pragma unroll
        for (int c = 0; c < 8; c++) { s1p[c] = 0.f; s2p[c] = 0.f; }
    }
#pragma unroll
    for (int rp = 0; rp < 4; rp++) {
#pragma unroll
        for (int h = 0; h < 2; h++) {
            int lr = ty * 8 + rp * 2 + h;
            bool valid = lr < rows;
            float hv[8];
#pragma unroll
            for (int c = 0; c < 8; c++) {
                float2 f = unpack2(acc[rp * 8 + c]);
                hv[c] = h ? f.y : f.x;
                if (FIRST) hv[c] = fmaxf(hv[c], 0.f);
            }
            if (valid) {
                float4* dst = (float4*)(out + (size_t)(row0 + lr) * NHID + tx * 8);
                dst[0] = make_float4(hv[0], hv[1], hv[2], hv[3]);
                dst[1] = make_float4(hv[4], hv[5], hv[6], hv[7]);
                if (FIRST) {
#pragma unroll
                    for (int c = 0; c < 8; c++) {
                        s1p[c] += hv[c];
                        s2p[c] += hv[c] * hv[c];
                    }
                }
            }
        }
    }
    if (FIRST) {
        // block reduction of BN stats in SMEM (reuse Asm region)
        __syncthreads();
        float* red = Asm;    // 8 x 128
        ((float4*)(red + ty * 128 + tx * 8))[0] = make_float4(s1p[0], s1p[1], s1p[2], s1p[3]);
        ((float4*)(red + ty * 128 + tx * 8))[1] = make_float4(s1p[4], s1p[5], s1p[6], s1p[7]);
        __syncthreads();
        float t1 = 0.f;
#pragma unroll
        for (int j = 0; j < 8; j++) t1 += red[j * 128 + tid];
        atomicAdd(&g_sum[tid], t1);
        __syncthreads();
        ((float4*)(red + ty * 128 + tx * 8))[0] = make_float4(s2p[0], s2p[1], s2p[2], s2p[3]);
        ((float4*)(red + ty * 128 + tx * 8))[1] = make_float4(s2p[4], s2p[5], s2p[6], s2p[7]);
        __syncthreads();
        float t2 = 0.f;
#pragma unroll
        for (int j = 0; j < 8; j++) t2 += red[j * 128 + tid];
        atomicAdd(&g_sumsq[tid], t2);
    }
}

// ---------------- launch ------------------------------------------------------
extern "C" void kernel_launch(void* const* d_in, const int* in_sizes, int n_in,
                              void* d_out, int out_size) {
    const float* x     = (const float*)d_in[0];
    const int*   ei    = (const int*)d_in[1];
    const float* W1    = (const float*)d_in[2];
    const float* b1    = (const float*)d_in[3];
    const float* gamma = (const float*)d_in[4];
    const float* beta  = (const float*)d_in[5];
    const float* W2    = (const float*)d_in[6];
    const float* b2    = (const float*)d_in[7];
    float* out = (float*)d_out;

    float* agg_p; cudaGetSymbolAddress((void**)&agg_p, g_agg);
    float* h_p;   cudaGetSymbolAddress((void**)&h_p, g_h);
    float* w1t_p; cudaGetSymbolAddress((void**)&w1t_p, g_W1T);
    float* w2t_p; cudaGetSymbolAddress((void**)&w2t_p, g_W2T);

    cudaFuncSetAttribute(gemm_kernel<true>,
                         cudaFuncAttributeMaxDynamicSharedMemorySize, GEMM_SMEM_BYTES);
    cudaFuncSetAttribute(gemm_kernel<false>,
                         cudaFuncAttributeMaxDynamicSharedMemorySize, GEMM_SMEM_BYTES);

    transpose_kernel<<<2, 256>>>(W1, W2);

    const int e8blocks = (N_EDGES / 8 + 255) / 256;
    hist_kernel<<<e8blocks, 256>>>(ei);
    partial_kernel<<<NBLK, 256>>>();
    offsets_kernel<<<NBLK, 256>>>();
    reorder_kernel<<<e8blocks, 256>>>(ei);

    gather_kernel<<<(N_NODES + 7) / 8, 256>>>(x);

    const int gblocks = (N_NODES + 63) / 64;
    gemm_kernel<true><<<gblocks, 128, GEMM_SMEM_BYTES>>>(
        agg_p, w1t_p, b1, h_p, nullptr, nullptr, nullptr, nullptr);
    gemm_kernel<false><<<gblocks, 128, GEMM_SMEM_BYTES>>>(
        h_p, w2t_p, nullptr, out, gamma, beta, W2, b2);
}

// round 8
// speedup vs baseline: 2.9824x; 1.4723x over previous
#include <cuda_runtime.h>
#include <cuda_bf16.h>

#define N_NODES 50000
#define N_EDGES 800000
#define NHID 128
#define BN_EPS 1e-5f
#define NBLK 196                 // ceil(50000/256)
#define NTILE 391                // ceil(50000/128)

typedef unsigned long long u64;
typedef unsigned int u32;

// ---------------- helpers ----------------------------------------------------
__device__ __forceinline__ u32 smem_u32(const void* p) {
    u32 a;
    asm("{ .reg .u64 t; cvta.to.shared.u64 t, %1; cvt.u32.u64 %0, t; }"
        : "=r"(a) : "l"(p));
    return a;
}
__device__ __forceinline__ void lds2(u32 addr, u32& a, u32& b) {
    asm volatile("ld.shared.v2.u32 {%0, %1}, [%2];" : "=r"(a), "=r"(b) : "r"(addr));
}
__device__ __forceinline__ void sts2f(u32 addr, float a, float b) {
    asm volatile("st.shared.v2.f32 [%0], {%1, %2};" :: "r"(addr), "f"(a), "f"(b) : "memory");
}
__device__ __forceinline__ void mma16816(float* c, u32 a0, u32 a1, u32 a2, u32 a3,
                                         u32 b0, u32 b1) {
    asm volatile(
        "mma.sync.aligned.m16n8k16.row.col.f32.bf16.bf16.f32 "
        "{%0,%1,%2,%3}, {%4,%5,%6,%7}, {%8,%9}, {%0,%1,%2,%3};"
        : "+f"(c[0]), "+f"(c[1]), "+f"(c[2]), "+f"(c[3])
        : "r"(a0), "r"(a1), "r"(a2), "r"(a3), "r"(b0), "r"(b1));
}
// split float4 -> interleaved uint4 {hi01, lo01, hi23, lo23} (bf16x2 words)
__device__ __forceinline__ uint4 split4i(float4 v) {
    __nv_bfloat162 h0 = __float22bfloat162_rn(make_float2(v.x, v.y));
    __nv_bfloat162 h1 = __float22bfloat162_rn(make_float2(v.z, v.w));
    float2 r0 = make_float2(v.x - __bfloat162float(h0.x), v.y - __bfloat162float(h0.y));
    float2 r1 = make_float2(v.z - __bfloat162float(h1.x), v.w - __bfloat162float(h1.y));
    __nv_bfloat162 l0 = __float22bfloat162_rn(r0);
    __nv_bfloat162 l1 = __float22bfloat162_rn(r1);
    uint4 q;
    q.x = *(u32*)&h0; q.y = *(u32*)&l0;
    q.z = *(u32*)&h1; q.w = *(u32*)&l1;
    return q;
}

// ---------------- scratch ----------------------------------------------------
__device__ float g_sum[NHID];
__device__ float g_sumsq[NHID];
__device__ float g_c2[NHID];
__device__ int   g_count[N_NODES];
__device__ int   g_off[N_NODES + 1];
__device__ int   g_cursor[N_NODES];
__device__ int   g_srcsorted[N_EDGES];
__device__ int   g_bsum[NBLK];
// interleaved hi/lo bf16: per row 64 u64 slots (slot j = k pair 2j,2j+1)
__device__ __align__(16) unsigned char g_Ahl[(size_t)NTILE * 65536];
__device__ __align__(16) unsigned char g_Hhl[(size_t)NTILE * 65536];
__device__ __align__(16) unsigned char g_W1hl[65536];
__device__ __align__(16) unsigned char g_W2hl[65536];

// ---------------- front-end kernels (proven) ---------------------------------
__global__ __launch_bounds__(256) void hist_kernel(const int* __restrict__ ei) {
    const int n8 = N_EDGES / 8;
    int idx = blockIdx.x * blockDim.x + threadIdx.x;
    if (idx >= n8) return;
    const int4* d4 = (const int4*)(ei + N_EDGES);
    int4 a = d4[idx];
    int4 b = d4[idx + n8];
    atomicAdd(&g_count[a.x], 1); atomicAdd(&g_count[a.y], 1);
    atomicAdd(&g_count[a.z], 1); atomicAdd(&g_count[a.w], 1);
    atomicAdd(&g_count[b.x], 1); atomicAdd(&g_count[b.y], 1);
    atomicAdd(&g_count[b.z], 1); atomicAdd(&g_count[b.w], 1);
}

__global__ __launch_bounds__(256) void partial_kernel() {
    int t = threadIdx.x;
    int i = blockIdx.x * 256 + t;
    int v = (i < N_NODES) ? g_count[i] : 0;
#pragma unroll
    for (int o = 16; o > 0; o >>= 1) v += __shfl_down_sync(~0u, v, o);
    __shared__ int ws[8];
    if ((t & 31) == 0) ws[t >> 5] = v;
    __syncthreads();
    if (t == 0) {
        int s = 0;
#pragma unroll
        for (int k = 0; k < 8; k++) s += ws[k];
        g_bsum[blockIdx.x] = s;
    }
}

__global__ __launch_bounds__(256) void offsets_kernel(const float* __restrict__ W1) {
    int t = threadIdx.x;
    int bid = blockIdx.x;
    if (bid == NBLK) {           // W1 -> interleaved bf16 hi/lo
        if (t < 128) {
            const float4* wr = (const float4*)(W1 + t * NHID);
            uint4* dst = (uint4*)g_W1hl + t * 32;
#pragma unroll 8
            for (int k4 = 0; k4 < 32; k4++) dst[k4] = split4i(wr[k4]);
        }
        return;
    }
    __shared__ int sb[256];
    __shared__ int sh[256];
    sb[t] = (t < NBLK) ? g_bsum[t] : 0;
    __syncthreads();
#pragma unroll
    for (int o = 1; o < 256; o <<= 1) {
        int u = (t >= o) ? sb[t - o] : 0;
        __syncthreads();
        sb[t] += u;
        __syncthreads();
    }
    int base = (bid > 0) ? sb[bid - 1] : 0;

    int i = bid * 256 + t;
    int v = (i < N_NODES) ? g_count[i] : 0;
    sh[t] = v;
    __syncthreads();
#pragma unroll
    for (int o = 1; o < 256; o <<= 1) {
        int u = (t >= o) ? sh[t - o] : 0;
        __syncthreads();
        sh[t] += u;
        __syncthreads();
    }
    int off = base + sh[t] - v;
    if (i < N_NODES) {
        g_off[i] = off;
        g_cursor[i] = off;
        g_count[i] = 0;
    } else if (i == N_NODES) {
        g_off[N_NODES] = N_EDGES;
    }
    if (bid == 0 && t < NHID) { g_sum[t] = 0.f; g_sumsq[t] = 0.f; }
}

__global__ __launch_bounds__(256) void reorder_kernel(const int* __restrict__ ei) {
    const int n8 = N_EDGES / 8;
    int idx = blockIdx.x * blockDim.x + threadIdx.x;
    if (idx >= n8) return;
    const int4* s4 = (const int4*)ei;
    const int4* d4 = (const int4*)(ei + N_EDGES);
    int4 sa = s4[idx], sb = s4[idx + n8];
    int4 da = d4[idx], db = d4[idx + n8];
    g_srcsorted[atomicAdd(&g_cursor[da.x], 1)] = sa.x;
    g_srcsorted[atomicAdd(&g_cursor[da.y], 1)] = sa.y;
    g_srcsorted[atomicAdd(&g_cursor[da.z], 1)] = sa.z;
    g_srcsorted[atomicAdd(&g_cursor[da.w], 1)] = sa.w;
    g_srcsorted[atomicAdd(&g_cursor[db.x], 1)] = sb.x;
    g_srcsorted[atomicAdd(&g_cursor[db.y], 1)] = sb.y;
    g_srcsorted[atomicAdd(&g_cursor[db.z], 1)] = sb.z;
    g_srcsorted[atomicAdd(&g_cursor[db.w], 1)] = sb.w;
}

__global__ __launch_bounds__(256) void gather_kernel(const float* __restrict__ x) {
    int node = (blockIdx.x * blockDim.x + threadIdx.x) >> 5;
    int lane = threadIdx.x & 31;
    if (node >= N_NODES) return;
    int start = g_off[node];
    int deg = g_off[node + 1] - start;
    float4 acc = ((const float4*)(x + (size_t)node * NHID))[lane];
    const int* sl = g_srcsorted + start;
    int j = 0;
    for (; j + 4 <= deg; j += 4) {
        int s0 = sl[j], s1 = sl[j + 1], s2 = sl[j + 2], s3 = sl[j + 3];
        float4 v0 = ((const float4*)(x + (size_t)s0 * NHID))[lane];
        float4 v1 = ((const float4*)(x + (size_t)s1 * NHID))[lane];
        float4 v2 = ((const float4*)(x + (size_t)s2 * NHID))[lane];
        float4 v3 = ((const float4*)(x + (size_t)s3 * NHID))[lane];
        acc.x += v0.x + v1.x + v2.x + v3.x;
        acc.y += v0.y + v1.y + v2.y + v3.y;
        acc.z += v0.z + v1.z + v2.z + v3.z;
        acc.w += v0.w + v1.w + v2.w + v3.w;
    }
    for (; j < deg; j++) {
        int s0 = sl[j];
        float4 v0 = ((const float4*)(x + (size_t)s0 * NHID))[lane];
        acc.x += v0.x; acc.y += v0.y; acc.z += v0.z; acc.w += v0.w;
    }
    ((uint4*)g_Ahl)[(size_t)node * 32 + lane] = split4i(acc);
}

__global__ __launch_bounds__(128) void w2prep_kernel(
    const float* __restrict__ gamma, const float* __restrict__ beta,
    const float* __restrict__ W2, const float* __restrict__ b2) {
    __shared__ float sA[NHID], sB[NHID];
    int t = threadIdx.x;
    float mean = g_sum[t] * (1.f / N_NODES);
    float var = g_sumsq[t] * (1.f / N_NODES) - mean * mean;
    float a = gamma[t] * rsqrtf(var + BN_EPS);
    sA[t] = a;
    sB[t] = beta[t] - mean * a;
    __syncthreads();
    float c = b2[t];
    const float4* wr = (const float4*)(W2 + t * NHID);
    uint4* dst = (uint4*)g_W2hl + t * 32;
#pragma unroll 8
    for (int k4 = 0; k4 < 32; k4++) {
        float4 w = wr[k4];
        int k = k4 * 4;
        c += w.x * sB[k] + w.y * sB[k + 1] + w.z * sB[k + 2] + w.w * sB[k + 3];
        w.x *= sA[k]; w.y *= sA[k + 1]; w.z *= sA[k + 2]; w.w *= sA[k + 3];
        dst[k4] = split4i(w);
    }
    g_c2[t] = c;
}

// ---------------- HMMA GEMM: D[128x128] = (Ah+Al)(Wh+Wl)^T -------------------
// 256 thr = 8 warps, warp-tile m32 x n64: wr=wid>>1 rows 32wr.., wc=wid&1
// cols 64wc.. . SMEM: A,W as u64 slots [row][66] (slot=k-pair, hi|lo packed).
#define SROW 66                       // u64 per row (64 + 2 pad)
#define A_BYTES (128 * SROW * 8)      // 67584
#define GSM_BYTES (2 * A_BYTES + 512)

template <bool FIRST>
__global__ __launch_bounds__(256) void mma_kernel(
    const unsigned char* __restrict__ Ahl, const unsigned char* __restrict__ Whl,
    const float* __restrict__ bias,
    unsigned char* __restrict__ outHhl, float* __restrict__ outF) {
    extern __shared__ unsigned char sm[];
    const u32 smb = smem_u32(sm);
    const u32 aw = smb;
    const u32 bw = smb + A_BYTES;
    float* biasS = (float*)(sm + 2 * A_BYTES);
    float* ht = (float*)sm;           // 128 x 132 fp32 overlay (epilogue)

    const int tid = threadIdx.x;
    const int wid = tid >> 5;
    const int lane = tid & 31;
    const int g = lane >> 2;
    const int tig = lane & 3;
    const int wr = wid >> 1;
    const int wc = wid & 1;
    const int r0 = wr * 32;
    const int nbase = wc * 64;
    const int bidx = blockIdx.x;
    const int rows = min(128, N_NODES - bidx * 128);

    // ---- stage tiles: global [row][32 uint4] -> smem [row][33 uint4] ----
    {
        const uint4* gA = (const uint4*)Ahl + (size_t)bidx * 4096;
        const uint4* gW = (const uint4*)Whl;
        uint4* sA4 = (uint4*)sm;
        uint4* sW4 = (uint4*)(sm + A_BYTES);
#pragma unroll
        for (int it = 0; it < 16; it++) {
            int i = it * 256 + tid;
            int row = i >> 5, c4 = i & 31;
            sA4[row * 33 + c4] = gA[i];
            sW4[row * 33 + c4] = gW[i];
        }
        if (tid < 128) biasS[tid] = bias[tid];
    }
    __syncthreads();

    // ---- mainloop ----
    float acc[2][8][4];
#pragma unroll
    for (int rs = 0; rs < 2; rs++)
#pragma unroll
        for (int nb = 0; nb < 8; nb++)
#pragma unroll
            for (int q = 0; q < 4; q++) acc[rs][nb][q] = 0.f;

    for (int ks = 0; ks < 8; ks++) {
        const int kb2 = ks * 8;
        u32 ah[2][4], al[2][4];
#pragma unroll
        for (int rs = 0; rs < 2; rs++) {
            int rb = r0 + rs * 16 + g;
            lds2(aw + (rb * SROW + tig + kb2) * 8,       ah[rs][0], al[rs][0]);
            lds2(aw + ((rb + 8) * SROW + tig + kb2) * 8, ah[rs][1], al[rs][1]);
            lds2(aw + (rb * SROW + tig + 4 + kb2) * 8,       ah[rs][2], al[rs][2]);
            lds2(aw + ((rb + 8) * SROW + tig + 4 + kb2) * 8, ah[rs][3], al[rs][3]);
        }
#pragma unroll
        for (int nb = 0; nb < 8; nb++) {
            int nn = nbase + nb * 8 + g;
            u32 b0h, b0l, b1h, b1l;
            lds2(bw + (nn * SROW + tig + kb2) * 8,     b0h, b0l);
            lds2(bw + (nn * SROW + tig + 4 + kb2) * 8, b1h, b1l);
#pragma unroll
            for (int rs = 0; rs < 2; rs++) {
                mma16816(acc[rs][nb], ah[rs][0], ah[rs][1], ah[rs][2], ah[rs][3], b0h, b1h);
                mma16816(acc[rs][nb], ah[rs][0], ah[rs][1], ah[rs][2], ah[rs][3], b0l, b1l);
                mma16816(acc[rs][nb], al[rs][0], al[rs][1], al[rs][2], al[rs][3], b0h, b1h);
            }
        }
    }
    __syncthreads();   // done reading A/W smem; reuse as ht

    // ---- store fragments -> ht (bias, relu, row mask) ----
#pragma unroll
    for (int rs = 0; rs < 2; rs++) {
#pragma unroll
        for (int nb = 0; nb < 8; nb++) {
            int row = r0 + rs * 16 + g;
            int col = nbase + nb * 8 + 2 * tig;
            float bc0 = biasS[col], bc1 = biasS[col + 1];
            float v0 = acc[rs][nb][0] + bc0, v1 = acc[rs][nb][1] + bc1;
            float v2 = acc[rs][nb][2] + bc0, v3 = acc[rs][nb][3] + bc1;
            if (FIRST) {
                v0 = fmaxf(v0, 0.f); v1 = fmaxf(v1, 0.f);
                v2 = fmaxf(v2, 0.f); v3 = fmaxf(v3, 0.f);
            }
            if (row >= rows) { v0 = 0.f; v1 = 0.f; }
            if (row + 8 >= rows) { v2 = 0.f; v3 = 0.f; }
            sts2f(smb + (row * 132 + col) * 4, v0, v1);
            sts2f(smb + ((row + 8) * 132 + col) * 4, v2, v3);
        }
    }
    __syncthreads();

    // ---- epilogue ----
    if (FIRST) {
        if (tid < 128) {
            float s1 = 0.f, s2 = 0.f;
#pragma unroll 8
            for (int r = 0; r < 128; r++) {
                float v = ht[r * 132 + tid];
                s1 += v;
                s2 += v * v;
            }
            atomicAdd(&g_sum[tid], s1);
            atomicAdd(&g_sumsq[tid], s2);
        }
        uint4* oh = (uint4*)outHhl + (size_t)bidx * 4096;
        for (int i = tid; i < 4096; i += 256) {
            int row = i >> 5, c4 = i & 31;
            float4 v = *(float4*)&ht[row * 132 + c4 * 4];
            oh[row * 32 + c4] = split4i(v);
        }
    } else {
        for (int i = tid; i < 4096; i += 256) {
            int row = i >> 5, c4 = i & 31;
            if (row < rows) {
                float4 v = *(float4*)&ht[row * 132 + c4 * 4];
                ((float4*)(outF + (size_t)(bidx * 128 + row) * NHID))[c4] = v;
            }
        }
    }
}

// ---------------- launch ------------------------------------------------------
extern "C" void kernel_launch(void* const* d_in, const int* in_sizes, int n_in,
                              void* d_out, int out_size) {
    const float* x     = (const float*)d_in[0];
    const int*   ei    = (const int*)d_in[1];
    const float* W1    = (const float*)d_in[2];
    const float* b1    = (const float*)d_in[3];
    const float* gamma = (const float*)d_in[4];
    const float* beta  = (const float*)d_in[5];
    const float* W2    = (const float*)d_in[6];
    const float* b2    = (const float*)d_in[7];
    float* out = (float*)d_out;

    unsigned char *ahl, *hhl, *w1hl, *w2hl;
    float* c2p;
    cudaGetSymbolAddress((void**)&ahl, g_Ahl);
    cudaGetSymbolAddress((void**)&hhl, g_Hhl);
    cudaGetSymbolAddress((void**)&w1hl, g_W1hl);
    cudaGetSymbolAddress((void**)&w2hl, g_W2hl);
    cudaGetSymbolAddress((void**)&c2p, g_c2);

    cudaFuncSetAttribute(mma_kernel<true>,
                         cudaFuncAttributeMaxDynamicSharedMemorySize, GSM_BYTES);
    cudaFuncSetAttribute(mma_kernel<false>,
                         cudaFuncAttributeMaxDynamicSharedMemorySize, GSM_BYTES);

    const int e8blocks = (N_EDGES / 8 + 255) / 256;
    hist_kernel<<<e8blocks, 256>>>(ei);
    partial_kernel<<<NBLK, 256>>>();
    offsets_kernel<<<NBLK + 1, 256>>>(W1);
    reorder_kernel<<<e8blocks, 256>>>(ei);
    gather_kernel<<<(N_NODES + 7) / 8, 256>>>(x);

    mma_kernel<true><<<NTILE, 256, GSM_BYTES>>>(ahl, w1hl, b1, hhl, nullptr);
    w2prep_kernel<<<1, 128>>>(gamma, beta, W2, b2);
    mma_kernel<false><<<NTILE, 256, GSM_BYTES>>>(hhl, w2hl, c2p, nullptr, out);
}